// round 4
// baseline (speedup 1.0000x reference)
#include <cuda_runtime.h>
#include <math.h>

// ChamferLoss: bs=4, npts=4096, dim=3.
// dist^2(q, r) = ||q||^2 + (||r||^2 - 2 q.r)  -> 3 packed FMAs per 2 refs.
// Running min: 4 independent scalar FMNMX chains (unpack of 64b pair is free).
// smem: SoA groups of 4 refs: [ -2rx*4 | -2ry*4 | -2rz*4 | ||r||^2*4 ] (64B/group).

#define NPTS 4096
#define BS   4
#define TPB  256
#define QTILE TPB                    // 1 query per thread
#define NQT  (NPTS / QTILE)          // 16 query tiles
#define NBLK (NQT * BS * 2)          // 128 blocks == one balanced wave
#define SMEM_BYTES (NPTS * 4 * 4)    // 65536

__device__ float g_partial[NBLK];
__device__ unsigned int g_count = 0;

__device__ __forceinline__ unsigned long long bcast2(float f) {
    unsigned long long v;
    asm("mov.b64 %0, {%1, %1};" : "=l"(v) : "r"(__float_as_uint(f)));
    return v;
}
__device__ __forceinline__ void unpack2(unsigned long long v, float& a, float& b) {
    unsigned lo, hi;
    asm("mov.b64 {%0, %1}, %2;" : "=r"(lo), "=r"(hi) : "l"(v));
    a = __uint_as_float(lo); b = __uint_as_float(hi);
}

__global__ __launch_bounds__(TPB) void chamfer_kernel(
    const float* __restrict__ x, const float* __restrict__ y, float* __restrict__ out)
{
    extern __shared__ float s[];          // 16384 floats = 64KB
    __shared__ float red[8];
    __shared__ int   s_last;

    const int tid = threadIdx.x;
    const int qt  = blockIdx.x;
    const int b   = blockIdx.y;
    const int dir = blockIdx.z;           // 0: query=x ref=y ; 1: query=y ref=x

    const float* __restrict__ q  = dir ? y : x;
    const float* __restrict__ r  = dir ? x : y;
    const float* __restrict__ rb = r + (size_t)b * NPTS * 3;

    // Stage refs: -2r (SoA, 4-wide groups) and ||r||^2.
    #pragma unroll 4
    for (int i = tid; i < NPTS; i += TPB) {
        float rx = rb[3 * i + 0];
        float ry = rb[3 * i + 1];
        float rz = rb[3 * i + 2];
        float* base = s + ((i >> 2) << 4) + (i & 3);
        base[0]  = -2.0f * rx;
        base[4]  = -2.0f * ry;
        base[8]  = -2.0f * rz;
        base[12] = fmaf(rx, rx, fmaf(ry, ry, rz * rz));
    }

    // This thread's query point.
    const int qi = qt * QTILE + tid;
    const float* qp = q + ((size_t)b * NPTS + qi) * 3;
    const float qx = qp[0], qy = qp[1], qz = qp[2];
    const float qsq = fmaf(qx, qx, fmaf(qy, qy, qz * qz));
    const unsigned long long bx = bcast2(qx), by = bcast2(qy), bz = bcast2(qz);

    __syncthreads();

    unsigned sa = (unsigned)__cvta_generic_to_shared(s);
    float m0 = 3.402823466e+38f, m1 = m0, m2 = m0, m3 = m0;

    #pragma unroll 8
    for (int g = 0; g < NPTS / 4; ++g, sa += 64) {
        unsigned long long X01, X23, Y01, Y23, Z01, Z23, H01, H23;
        asm("ld.shared.v2.u64 {%0,%1}, [%2];"    : "=l"(X01), "=l"(X23) : "r"(sa));
        asm("ld.shared.v2.u64 {%0,%1}, [%2+16];" : "=l"(Y01), "=l"(Y23) : "r"(sa));
        asm("ld.shared.v2.u64 {%0,%1}, [%2+32];" : "=l"(Z01), "=l"(Z23) : "r"(sa));
        asm("ld.shared.v2.u64 {%0,%1}, [%2+48];" : "=l"(H01), "=l"(H23) : "r"(sa));

        unsigned long long t0, t1;
        asm("fma.rn.f32x2 %0, %1, %2, %3;" : "=l"(t0) : "l"(bx), "l"(X01), "l"(H01));
        asm("fma.rn.f32x2 %0, %1, %2, %0;" : "+l"(t0) : "l"(by), "l"(Y01));
        asm("fma.rn.f32x2 %0, %1, %2, %0;" : "+l"(t0) : "l"(bz), "l"(Z01));
        asm("fma.rn.f32x2 %0, %1, %2, %3;" : "=l"(t1) : "l"(bx), "l"(X23), "l"(H23));
        asm("fma.rn.f32x2 %0, %1, %2, %0;" : "+l"(t1) : "l"(by), "l"(Y23));
        asm("fma.rn.f32x2 %0, %1, %2, %0;" : "+l"(t1) : "l"(bz), "l"(Z23));

        float a0, a1, a2, a3;
        unpack2(t0, a0, a1);
        unpack2(t1, a2, a3);
        m0 = fminf(m0, a0);
        m1 = fminf(m1, a1);
        m2 = fminf(m2, a2);
        m3 = fminf(m3, a3);
    }

    float m = fminf(fminf(m0, m1), fminf(m2, m3));
    float v = sqrtf(1e-6f + qsq + m);

    // Deterministic block sum: 8 warps.
    #pragma unroll
    for (int off = 16; off; off >>= 1)
        v += __shfl_down_sync(0xFFFFFFFFu, v, off);
    if ((tid & 31) == 0) red[tid >> 5] = v;
    __syncthreads();

    const int bid = (dir * BS + b) * NQT + qt;
    if (tid == 0) {
        float t = 0.f;
        #pragma unroll
        for (int i = 0; i < 8; ++i) t += red[i];
        g_partial[bid] = t;
        __threadfence();
        unsigned old = atomicAdd(&g_count, 1u);
        s_last = (old == NBLK - 1) ? 1 : 0;
    }
    __syncthreads();

    // Last block: fixed-order final reduction (deterministic), reset counter.
    if (s_last) {
        volatile float* gp = g_partial;
        float w = (tid < NBLK) ? gp[tid] : 0.0f;
        #pragma unroll
        for (int off = 16; off; off >>= 1)
            w += __shfl_down_sync(0xFFFFFFFFu, w, off);
        if ((tid & 31) == 0) red[tid >> 5] = w;
        __syncthreads();
        if (tid == 0) {
            float t = 0.f;
            #pragma unroll
            for (int i = 0; i < 8; ++i) t += red[i];
            out[0] = t * (1.0f / 16384.0f);   // (S1 + S2) / (BS*NPTS)
            g_count = 0;                       // self-reset for graph replay
        }
    }
}

extern "C" void kernel_launch(void* const* d_in, const int* in_sizes, int n_in,
                              void* d_out, int out_size)
{
    const float* x = (const float*)d_in[0];
    const float* y = (const float*)d_in[1];
    float* out = (float*)d_out;

    cudaFuncSetAttribute(chamfer_kernel,
                         cudaFuncAttributeMaxDynamicSharedMemorySize, SMEM_BYTES);
    chamfer_kernel<<<dim3(NQT, BS, 2), TPB, SMEM_BYTES>>>(x, y, out);
}

// round 5
// speedup vs baseline: 1.5655x; 1.5655x over previous
#include <cuda_runtime.h>
#include <math.h>

// ChamferLoss: bs=4, npts=4096, dim=3.
// dist^2(q,r) = ||q||^2 + (||r||^2 - 2 q.r); minimize squared dist, sqrt once.
// Register-blocked: each thread holds Q=4 queries; each loaded ref group (4 refs,
// packed f32x2) feeds 4 queries -> 24 fma2 per 64B of LDS.
// Reference set split RS=4 ways across blocks; per-query partial mins combined
// in a small second kernel. smem group layout: [-2rx*4 | -2ry*4 | -2rz*4 | ||r||^2*4].

#define NPTS 4096
#define BS   4
#define TPB  256
#define Q    4                       // queries per thread
#define RS   4                       // reference splits
#define RPB  (NPTS / RS)             // 1024 refs per block
#define QPB  (TPB * Q)               // 1024 queries per block
#define NQT  (NPTS / QPB)            // 4 query tiles
#define NBLK (NQT * BS * 2 * RS)     // 128 blocks == one balanced wave

__device__ float g_pmin[2 * BS * NPTS * RS];   // [dir][b][q][rs]

__device__ __forceinline__ unsigned long long bcast2(float f) {
    unsigned long long v;
    asm("mov.b64 %0, {%1, %1};" : "=l"(v) : "r"(__float_as_uint(f)));
    return v;
}
__device__ __forceinline__ void unpack2(unsigned long long v, float& a, float& b) {
    unsigned lo, hi;
    asm("mov.b64 {%0, %1}, %2;" : "=r"(lo), "=r"(hi) : "l"(v));
    a = __uint_as_float(lo); b = __uint_as_float(hi);
}

__global__ __launch_bounds__(TPB, 1) void chamfer_main(
    const float* __restrict__ x, const float* __restrict__ y)
{
    __shared__ float s[RPB * 4];          // 16 KB

    const int tid = threadIdx.x;
    const int qt  = blockIdx.x;           // 0..NQT-1
    const int b   = blockIdx.y;           // 0..BS-1
    const int z   = blockIdx.z;           // 0..2*RS-1
    const int dir = z >> 2;               // z / RS
    const int rs  = z & 3;                // z % RS

    const float* __restrict__ q  = dir ? y : x;
    const float* __restrict__ r  = dir ? x : y;
    const float* __restrict__ rb = r + ((size_t)b * NPTS + (size_t)rs * RPB) * 3;

    // Stage this block's reference slice: -2r (SoA groups of 4) and ||r||^2.
    #pragma unroll 4
    for (int i = tid; i < RPB; i += TPB) {
        float rx = rb[3 * i + 0];
        float ry = rb[3 * i + 1];
        float rz = rb[3 * i + 2];
        float* base = s + ((i >> 2) << 4) + (i & 3);
        base[0]  = -2.0f * rx;
        base[4]  = -2.0f * ry;
        base[8]  = -2.0f * rz;
        base[12] = fmaf(rx, rx, fmaf(ry, ry, rz * rz));
    }

    // Q=4 query points per thread (coalesced loads within each k).
    const int qbase = qt * QPB + tid;
    unsigned long long bx[Q], by[Q], bz[Q];
    float qsq[Q];
    #pragma unroll
    for (int k = 0; k < Q; ++k) {
        const float* qp = q + ((size_t)b * NPTS + (qbase + k * TPB)) * 3;
        float qx = qp[0], qy = qp[1], qz = qp[2];
        qsq[k] = fmaf(qx, qx, fmaf(qy, qy, qz * qz));
        bx[k] = bcast2(qx); by[k] = bcast2(qy); bz[k] = bcast2(qz);
    }

    __syncthreads();

    unsigned sa = (unsigned)__cvta_generic_to_shared(s);
    float mac[Q][4];
    #pragma unroll
    for (int k = 0; k < Q; ++k) {
        mac[k][0] = 3.402823466e+38f; mac[k][1] = 3.402823466e+38f;
        mac[k][2] = 3.402823466e+38f; mac[k][3] = 3.402823466e+38f;
    }

    #pragma unroll 4
    for (int g = 0; g < RPB / 4; ++g, sa += 64) {
        unsigned long long X01, X23, Y01, Y23, Z01, Z23, H01, H23;
        asm("ld.shared.v2.u64 {%0,%1}, [%2];"    : "=l"(X01), "=l"(X23) : "r"(sa));
        asm("ld.shared.v2.u64 {%0,%1}, [%2+16];" : "=l"(Y01), "=l"(Y23) : "r"(sa));
        asm("ld.shared.v2.u64 {%0,%1}, [%2+32];" : "=l"(Z01), "=l"(Z23) : "r"(sa));
        asm("ld.shared.v2.u64 {%0,%1}, [%2+48];" : "=l"(H01), "=l"(H23) : "r"(sa));

        #pragma unroll
        for (int k = 0; k < Q; ++k) {
            unsigned long long t0, t1;
            asm("fma.rn.f32x2 %0, %1, %2, %3;" : "=l"(t0) : "l"(bz[k]), "l"(Z01), "l"(H01));
            asm("fma.rn.f32x2 %0, %1, %2, %0;" : "+l"(t0) : "l"(by[k]), "l"(Y01));
            asm("fma.rn.f32x2 %0, %1, %2, %0;" : "+l"(t0) : "l"(bx[k]), "l"(X01));
            asm("fma.rn.f32x2 %0, %1, %2, %3;" : "=l"(t1) : "l"(bz[k]), "l"(Z23), "l"(H23));
            asm("fma.rn.f32x2 %0, %1, %2, %0;" : "+l"(t1) : "l"(by[k]), "l"(Y23));
            asm("fma.rn.f32x2 %0, %1, %2, %0;" : "+l"(t1) : "l"(bx[k]), "l"(X23));
            float a0, a1, a2, a3;
            unpack2(t0, a0, a1);
            unpack2(t1, a2, a3);
            mac[k][0] = fminf(mac[k][0], a0);
            mac[k][1] = fminf(mac[k][1], a1);
            mac[k][2] = fminf(mac[k][2], a2);
            mac[k][3] = fminf(mac[k][3], a3);
        }
    }

    // Write per-query partial (qsq + min over this ref slice).
    const size_t obase = ((size_t)(dir * BS + b) * NPTS);
    #pragma unroll
    for (int k = 0; k < Q; ++k) {
        float m = fminf(fminf(mac[k][0], mac[k][1]), fminf(mac[k][2], mac[k][3]));
        g_pmin[(obase + (qbase + k * TPB)) * RS + rs] = qsq[k] + m;
    }
}

#define FTPB 1024
#define NCOMB (2 * BS * NPTS)        // 32768 combined query slots

__global__ __launch_bounds__(FTPB) void chamfer_finalize(float* __restrict__ out)
{
    __shared__ float red[32];
    const int tid = threadIdx.x;
    const float4* __restrict__ pm = (const float4*)g_pmin;

    float v = 0.0f;
    #pragma unroll
    for (int qq = 0; qq < NCOMB / FTPB; ++qq) {     // 32 iterations, coalesced
        float4 p = pm[qq * FTPB + tid];
        float m = fminf(fminf(p.x, p.y), fminf(p.z, p.w));
        v += sqrtf(1e-6f + m);
    }

    #pragma unroll
    for (int off = 16; off; off >>= 1)
        v += __shfl_down_sync(0xFFFFFFFFu, v, off);
    if ((tid & 31) == 0) red[tid >> 5] = v;
    __syncthreads();
    if (tid == 0) {
        float t = 0.0f;
        #pragma unroll
        for (int i = 0; i < 32; ++i) t += red[i];
        out[0] = t * (1.0f / 16384.0f);   // (S1 + S2) / (BS * NPTS)
    }
}

extern "C" void kernel_launch(void* const* d_in, const int* in_sizes, int n_in,
                              void* d_out, int out_size)
{
    const float* x = (const float*)d_in[0];
    const float* y = (const float*)d_in[1];
    float* out = (float*)d_out;

    chamfer_main<<<dim3(NQT, BS, 2 * RS), TPB>>>(x, y);
    chamfer_finalize<<<1, FTPB>>>(out);
}

// round 6
// speedup vs baseline: 1.9835x; 1.2670x over previous
#include <cuda_runtime.h>
#include <math.h>

// ChamferLoss: bs=4, npts=4096, dim=3.
// dist^2(q,r) = ||q||^2 + (||r||^2 - 2 q.r); minimize squared dist, sqrt once.
// Register-blocked: each thread holds Q=4 queries; each loaded ref group (4 refs,
// packed f32x2) feeds 4 queries -> 24 fma2 per 64B of LDS.
// Reference set split RS=4 ways across blocks. Combine + sqrt + reduction are
// distributed across per-group finisher blocks via self-resetting counters
// (single kernel, graph-replayable, deterministic summation order).

#define NPTS 4096
#define BS   4
#define TPB  256
#define Q    4                       // queries per thread
#define RS   4                       // reference splits
#define RPB  (NPTS / RS)             // 1024 refs per block
#define QPB  (TPB * Q)               // 1024 queries per block
#define NQT  (NPTS / QPB)            // 4 query tiles
#define NGRP (NQT * BS * 2)          // 32 query-tile groups
#define NBLK (NGRP * RS)             // 128 blocks == one balanced wave

__device__ float g_pmin[2 * BS * NPTS * RS];   // [dir][b][q][rs]
__device__ float g_gsum[NGRP];
__device__ unsigned int g_gc[NGRP];            // zero-init, self-resetting
__device__ unsigned int g_fc;                  // zero-init, self-resetting

__device__ __forceinline__ unsigned long long bcast2(float f) {
    unsigned long long v;
    asm("mov.b64 %0, {%1, %1};" : "=l"(v) : "r"(__float_as_uint(f)));
    return v;
}
__device__ __forceinline__ void unpack2(unsigned long long v, float& a, float& b) {
    unsigned lo, hi;
    asm("mov.b64 {%0, %1}, %2;" : "=r"(lo), "=r"(hi) : "l"(v));
    a = __uint_as_float(lo); b = __uint_as_float(hi);
}

__global__ __launch_bounds__(TPB, 1) void chamfer_main(
    const float* __restrict__ x, const float* __restrict__ y, float* __restrict__ out)
{
    __shared__ float s[RPB * 4];          // 16 KB
    __shared__ float red[8];
    __shared__ int   s_last;

    const int tid = threadIdx.x;
    const int qt  = blockIdx.x;           // 0..NQT-1
    const int b   = blockIdx.y;           // 0..BS-1
    const int z   = blockIdx.z;           // 0..2*RS-1
    const int dir = z >> 2;               // z / RS
    const int rs  = z & 3;                // z % RS

    const float* __restrict__ q  = dir ? y : x;
    const float* __restrict__ r  = dir ? x : y;
    const float* __restrict__ rb = r + ((size_t)b * NPTS + (size_t)rs * RPB) * 3;

    // Stage this block's reference slice: -2r (SoA groups of 4) and ||r||^2.
    #pragma unroll 4
    for (int i = tid; i < RPB; i += TPB) {
        float rx = rb[3 * i + 0];
        float ry = rb[3 * i + 1];
        float rz = rb[3 * i + 2];
        float* base = s + ((i >> 2) << 4) + (i & 3);
        base[0]  = -2.0f * rx;
        base[4]  = -2.0f * ry;
        base[8]  = -2.0f * rz;
        base[12] = fmaf(rx, rx, fmaf(ry, ry, rz * rz));
    }

    // Q=4 query points per thread (coalesced loads within each k).
    const int qbase = qt * QPB + tid;
    unsigned long long bx[Q], by[Q], bz[Q];
    float qsq[Q];
    #pragma unroll
    for (int k = 0; k < Q; ++k) {
        const float* qp = q + ((size_t)b * NPTS + (qbase + k * TPB)) * 3;
        float qx = qp[0], qy = qp[1], qz = qp[2];
        qsq[k] = fmaf(qx, qx, fmaf(qy, qy, qz * qz));
        bx[k] = bcast2(qx); by[k] = bcast2(qy); bz[k] = bcast2(qz);
    }

    __syncthreads();

    unsigned sa = (unsigned)__cvta_generic_to_shared(s);
    float mac[Q][4];
    #pragma unroll
    for (int k = 0; k < Q; ++k) {
        mac[k][0] = 3.402823466e+38f; mac[k][1] = 3.402823466e+38f;
        mac[k][2] = 3.402823466e+38f; mac[k][3] = 3.402823466e+38f;
    }

    #pragma unroll 4
    for (int g = 0; g < RPB / 4; ++g, sa += 64) {
        unsigned long long X01, X23, Y01, Y23, Z01, Z23, H01, H23;
        asm("ld.shared.v2.u64 {%0,%1}, [%2];"    : "=l"(X01), "=l"(X23) : "r"(sa));
        asm("ld.shared.v2.u64 {%0,%1}, [%2+16];" : "=l"(Y01), "=l"(Y23) : "r"(sa));
        asm("ld.shared.v2.u64 {%0,%1}, [%2+32];" : "=l"(Z01), "=l"(Z23) : "r"(sa));
        asm("ld.shared.v2.u64 {%0,%1}, [%2+48];" : "=l"(H01), "=l"(H23) : "r"(sa));

        #pragma unroll
        for (int k = 0; k < Q; ++k) {
            unsigned long long t0, t1;
            asm("fma.rn.f32x2 %0, %1, %2, %3;" : "=l"(t0) : "l"(bz[k]), "l"(Z01), "l"(H01));
            asm("fma.rn.f32x2 %0, %1, %2, %0;" : "+l"(t0) : "l"(by[k]), "l"(Y01));
            asm("fma.rn.f32x2 %0, %1, %2, %0;" : "+l"(t0) : "l"(bx[k]), "l"(X01));
            asm("fma.rn.f32x2 %0, %1, %2, %3;" : "=l"(t1) : "l"(bz[k]), "l"(Z23), "l"(H23));
            asm("fma.rn.f32x2 %0, %1, %2, %0;" : "+l"(t1) : "l"(by[k]), "l"(Y23));
            asm("fma.rn.f32x2 %0, %1, %2, %0;" : "+l"(t1) : "l"(bx[k]), "l"(X23));
            float a0, a1, a2, a3;
            unpack2(t0, a0, a1);
            unpack2(t1, a2, a3);
            mac[k][0] = fminf(mac[k][0], a0);
            mac[k][1] = fminf(mac[k][1], a1);
            mac[k][2] = fminf(mac[k][2], a2);
            mac[k][3] = fminf(mac[k][3], a3);
        }
    }

    // Write per-query partial (qsq + min over this ref slice).
    const size_t obase = (size_t)(dir * BS + b) * NPTS;
    #pragma unroll
    for (int k = 0; k < Q; ++k) {
        float m = fminf(fminf(mac[k][0], mac[k][1]), fminf(mac[k][2], mac[k][3]));
        g_pmin[(obase + (qbase + k * TPB)) * RS + rs] = qsq[k] + m;
    }

    // ---- Distributed epilogue: last RS-block of each group combines. ----
    const int gidx = (dir * BS + b) * NQT + qt;
    __threadfence();
    if (tid == 0)
        s_last = (atomicAdd(&g_gc[gidx], 1u) == RS - 1) ? 1 : 0;
    __syncthreads();

    if (s_last) {
        if (tid == 0) g_gc[gidx] = 0;     // self-reset for graph replay
        const float4* pm = (const float4*)g_pmin;   // RS=4 partials per query
        float v = 0.0f;
        #pragma unroll
        for (int k = 0; k < Q; ++k) {
            float4 p = __ldcg(pm + (obase + (qbase + k * TPB)));
            float m = fminf(fminf(p.x, p.y), fminf(p.z, p.w));
            v += sqrtf(1e-6f + m);
        }
        #pragma unroll
        for (int off = 16; off; off >>= 1)
            v += __shfl_down_sync(0xFFFFFFFFu, v, off);
        if ((tid & 31) == 0) red[tid >> 5] = v;
        __syncthreads();
        if (tid == 0) {
            float t = 0.0f;
            #pragma unroll
            for (int i = 0; i < 8; ++i) t += red[i];
            g_gsum[gidx] = t;
            __threadfence();
            if (atomicAdd(&g_fc, 1u) == NGRP - 1) {
                float tot = 0.0f;
                volatile float* gs = g_gsum;
                #pragma unroll
                for (int i = 0; i < NGRP; ++i) tot += gs[i];
                out[0] = tot * (1.0f / 16384.0f);   // (S1 + S2) / (BS * NPTS)
                g_fc = 0;                            // self-reset for graph replay
            }
        }
    }
}

extern "C" void kernel_launch(void* const* d_in, const int* in_sizes, int n_in,
                              void* d_out, int out_size)
{
    const float* x = (const float*)d_in[0];
    const float* y = (const float*)d_in[1];
    float* out = (float*)d_out;

    chamfer_main<<<dim3(NQT, BS, 2 * RS), TPB>>>(x, y, out);
}